// round 14
// baseline (speedup 1.0000x reference)
#include <cuda_runtime.h>
#include <cuda_fp16.h>
#include <cstdint>

#define SEQ 2048
#define DM  1024
#define DK  64
#define NB  8

// ------------------------- scratch (device globals) -------------------------
__device__ __half g_Xh [NB * SEQ * DM];               // 32 MB (fp16 input)
__device__ __half g_QKh[NB * SEQ * 128];              //  4 MB (Q cols 0-63, K cols 64-127)
__device__ __half g_VTh[NB * DM * SEQ];               // 32 MB (V^T per batch)
__device__ __half g_Ph [(size_t)NB * SEQ * SEQ];      // 64 MB (P = exp(S/8), masked)
__device__ float  g_Lpart[NB * SEQ * 16];             //  1 MB
__device__ float  g_Linv[NB * SEQ];
__device__ __half g_WqkTh[128 * DM];                  // [Wq|Wk]^T fp16
__device__ __half g_WvTh [DM * DM];                   // Wv^T fp16
__device__ float  g_bqk  [128];

// ------------------------- helpers -------------------------
__device__ __forceinline__ void mma_f16(float* c, const uint32_t* a, const uint32_t* b) {
    asm volatile(
        "mma.sync.aligned.m16n8k16.row.col.f32.f16.f16.f32 "
        "{%0,%1,%2,%3}, {%4,%5,%6,%7}, {%8,%9}, {%0,%1,%2,%3};"
        : "+f"(c[0]), "+f"(c[1]), "+f"(c[2]), "+f"(c[3])
        : "r"(a[0]), "r"(a[1]), "r"(a[2]), "r"(a[3]), "r"(b[0]), "r"(b[1]));
}
__device__ __forceinline__ void ldsm4(uint32_t& r0, uint32_t& r1, uint32_t& r2,
                                      uint32_t& r3, uint32_t addr) {
    asm volatile("ldmatrix.sync.aligned.m8n8.x4.shared.b16 {%0,%1,%2,%3}, [%4];"
        : "=r"(r0), "=r"(r1), "=r"(r2), "=r"(r3) : "r"(addr));
}
__device__ __forceinline__ void cpasync16(uint32_t dst, uint64_t gsrc) {
    asm volatile("cp.async.cg.shared.global [%0], [%1], 16;" :: "r"(dst), "l"(gsrc) : "memory");
}
#define CP_COMMIT() asm volatile("cp.async.commit_group;" ::: "memory")
#define CP_WAIT2()  asm volatile("cp.async.wait_group 2;" ::: "memory")

// Smem tile: [rows][32 halves] = 64B/row = 4 16B-units/row.
// unit' = u ^ ((row>>1)&3)  -> cp.async stores and ldmatrix reads conflict-free.

// ---------------------------------------------------------------------------
// fp16 mma.sync GEMM (m16n8k16), K-major operands in gmem.
//   BM=128, BN = 128 (256 thr) or 256 (512 thr), BK=32, 4-stage cp.async.
//   outMode: 0 = float C (rowscale+bias+rowbias), 1 = half C (bias+rowbias),
//            2 = scoreExp (narrow only): half C = exp(acc/8) diag-masked -> lpart
// ---------------------------------------------------------------------------
template <int BN, int THREADS, int MINB>
__global__ __launch_bounds__(THREADS, MINB)
void mma_gemm(const __half* __restrict__ A, const __half* __restrict__ B,
              void* __restrict__ Cv, const float* __restrict__ bias,
              const float* __restrict__ rowbias,
              const float* __restrict__ rowscale, float* __restrict__ lpart,
              int N, int K, int lda, int ldb,
              int causalK, int causalSkip, int outMode,
              size_t sA, size_t sB, size_t sC, size_t sR)
{
    extern __shared__ uint32_t SM[];
    constexpr int WN = BN / 64;                 // warps along n (2 or 4)
    constexpr uint32_t BSTB = BN * 64u;         // B stage bytes
    constexpr uint32_t STG  = 8192u + BSTB;     // stage stride
    constexpr int UA = 512 / THREADS;           // A cp units per thread
    constexpr int UB = (BN * 4) / THREADS;      // B cp units per thread (=2)

    const int rb = blockIdx.y, cb = blockIdx.x, z = blockIdx.z;
    if (causalSkip && cb > rb) return;

    A += (size_t)z * sA;
    B += (size_t)z * sB;
    if (rowscale) rowscale += (size_t)z * sR;

    int kend = causalK ? (rb + 1) * 128 : K;
    if (kend > K) kend = K;
    const int NC = kend >> 5;

    const int tid = threadIdx.x, lane = tid & 31;
    const int wid = tid >> 5;
    const int wm = wid / WN;                    // 0..3
    const int wn = wid % WN;                    // 0..WN-1

    const __half* Ab = A + (size_t)rb * 128 * lda;
    const __half* Bb = B + (size_t)cb * BN * ldb;
    uint64_t gAb, gBb;
    asm("cvta.to.global.u64 %0, %1;" : "=l"(gAb) : "l"(Ab));
    asm("cvta.to.global.u64 %0, %1;" : "=l"(gBb) : "l"(Bb));
    const uint32_t smb = (uint32_t)__cvta_generic_to_shared(SM);

    uint32_t dstA[UA], dstB[UB];
    uint64_t offA[UA], offB[UB];
    #pragma unroll
    for (int it = 0; it < UA; it++) {
        int f = tid + it * THREADS;
        int r = f >> 2, u = f & 3;
        dstA[it] = smb + (uint32_t)(r * 64 + ((u ^ ((r >> 1) & 3)) << 4));
        offA[it] = ((uint64_t)r * lda + (uint64_t)u * 8) * 2u;
    }
    #pragma unroll
    for (int it = 0; it < UB; it++) {
        int f = tid + it * THREADS;
        int r = f >> 2, u = f & 3;
        dstB[it] = smb + 8192u + (uint32_t)(r * 64 + ((u ^ ((r >> 1) & 3)) << 4));
        offB[it] = ((uint64_t)r * ldb + (uint64_t)u * 8) * 2u;
    }

    uint32_t adrA[2][2], adrB[4][2];
    {
        const int rl = ((lane >> 3) & 1) * 8 + (lane & 7);
        const int cl = (lane >> 4) & 1;
        #pragma unroll
        for (int mi = 0; mi < 2; mi++) {
            int r = wm * 32 + mi * 16 + rl;
            #pragma unroll
            for (int ks = 0; ks < 2; ks++) {
                int u = 2 * ks + cl;
                adrA[mi][ks] = smb + (uint32_t)(r * 64 + ((u ^ ((r >> 1) & 3)) << 4));
            }
        }
        #pragma unroll
        for (int p = 0; p < 4; p++) {
            int n = wn * 64 + p * 16 + rl;
            #pragma unroll
            for (int ks = 0; ks < 2; ks++) {
                int u = 2 * ks + cl;
                adrB[p][ks] = smb + 8192u + (uint32_t)(n * 64 + ((u ^ ((n >> 1) & 3)) << 4));
            }
        }
    }

    float acc[2][8][4];
    #pragma unroll
    for (int i = 0; i < 2; i++)
        #pragma unroll
        for (int j = 0; j < 8; j++)
            #pragma unroll
            for (int q = 0; q < 4; q++) acc[i][j][q] = 0.f;

    auto issue = [&](int c, int stg) {
        const uint32_t so = (uint32_t)stg * STG;
        const uint64_t co = (uint64_t)c * 64u;
        #pragma unroll
        for (int it = 0; it < UA; it++)
            cpasync16(dstA[it] + so, gAb + co + offA[it]);
        #pragma unroll
        for (int it = 0; it < UB; it++)
            cpasync16(dstB[it] + so, gBb + co + offB[it]);
    };

    auto compute = [&](int stg) {
        const uint32_t bo = (uint32_t)stg * STG;
        #pragma unroll
        for (int ks = 0; ks < 2; ks++) {
            uint32_t a[2][4], b[8][2];
            #pragma unroll
            for (int mi = 0; mi < 2; mi++)
                ldsm4(a[mi][0], a[mi][1], a[mi][2], a[mi][3], adrA[mi][ks] + bo);
            #pragma unroll
            for (int p = 0; p < 4; p++)
                ldsm4(b[2 * p][0], b[2 * p + 1][0], b[2 * p][1], b[2 * p + 1][1],
                      adrB[p][ks] + bo);
            #pragma unroll
            for (int mi = 0; mi < 2; mi++)
                #pragma unroll
                for (int ni = 0; ni < 8; ni++)
                    mma_f16(acc[mi][ni], a[mi], b[ni]);
        }
    };

    #pragma unroll
    for (int s = 0; s < 3; s++) {
        if (s < NC) issue(s, s);
        CP_COMMIT();
    }
    for (int c = 0; c < NC; c++) {
        CP_WAIT2();
        __syncthreads();
        compute(c & 3);
        const int nc = c + 3;
        if (nc < NC) issue(nc, nc & 3);
        CP_COMMIT();
    }

    // ---------------- epilogue ----------------
    if (outMode == 2) {
        __half* C = (__half*)Cv + (size_t)z * sC;
        const bool diag = (cb == rb);
        float part[2][2] = {{0.f, 0.f}, {0.f, 0.f}};
        #pragma unroll
        for (int mi = 0; mi < 2; mi++) {
            int rbase = rb * 128 + wm * 32 + mi * 16 + (lane >> 2);
            #pragma unroll
            for (int half_ = 0; half_ < 2; half_++) {
                int row = rbase + half_ * 8;
                __half* Cp = C + (size_t)row * N;
                #pragma unroll
                for (int ni = 0; ni < 8; ni++) {
                    int col = cb * BN + wn * 64 + ni * 8 + ((lane & 3) << 1);
                    float e0 = __expf(acc[mi][ni][half_ * 2 + 0] * 0.125f);
                    float e1 = __expf(acc[mi][ni][half_ * 2 + 1] * 0.125f);
                    if (diag) {
                        if (col > row) e0 = 0.f;
                        if (col + 1 > row) e1 = 0.f;
                    }
                    part[mi][half_] += e0 + e1;
                    *reinterpret_cast<__half2*>(Cp + col) = __floats2half2_rn(e0, e1);
                }
            }
        }
        __syncthreads();
        float* rs = reinterpret_cast<float*>(SM);   // [128][WN]
        #pragma unroll
        for (int mi = 0; mi < 2; mi++)
            #pragma unroll
            for (int half_ = 0; half_ < 2; half_++) {
                float v = part[mi][half_];
                v += __shfl_xor_sync(0xFFFFFFFF, v, 1);
                v += __shfl_xor_sync(0xFFFFFFFF, v, 2);
                if ((lane & 3) == 0) {
                    int rl = wm * 32 + mi * 16 + half_ * 8 + (lane >> 2);
                    rs[rl * WN + wn] = v;
                }
            }
        __syncthreads();
        if (tid < 128) {
            float s = 0.f;
            #pragma unroll
            for (int w = 0; w < WN; w++) s += rs[tid * WN + w];
            lpart[(((size_t)z * SEQ) + rb * 128 + tid) * 16 + cb] = s;
        }
        return;
    }

    #pragma unroll
    for (int mi = 0; mi < 2; mi++) {
        int rbase = rb * 128 + wm * 32 + mi * 16 + (lane >> 2);
        #pragma unroll
        for (int half_ = 0; half_ < 2; half_++) {
            int row = rbase + half_ * 8;
            float sc = rowscale ? rowscale[row] : 1.0f;
            float rbv = rowbias ? rowbias[row] : 0.0f;
            #pragma unroll
            for (int ni = 0; ni < 8; ni++) {
                int col = cb * BN + wn * 64 + ni * 8 + ((lane & 3) << 1);
                float b0 = rbv, b1 = rbv;
                if (bias) { b0 += bias[col]; b1 += bias[col + 1]; }
                float o0 = acc[mi][ni][half_ * 2 + 0] * sc + b0;
                float o1 = acc[mi][ni][half_ * 2 + 1] * sc + b1;
                if (outMode == 1) {
                    __half* Cp = (__half*)Cv + (size_t)z * sC + (size_t)row * N;
                    *reinterpret_cast<__half2*>(Cp + col) = __floats2half2_rn(o0, o1);
                } else {
                    float* Cp = (float*)Cv + (size_t)z * sC + (size_t)row * N;
                    *reinterpret_cast<float2*>(Cp + col) = make_float2(o0, o1);
                }
            }
        }
    }
}

// ---------------------------------------------------------------------------
__global__ void conv_half(const float4* __restrict__ in, __half2* __restrict__ out, int n4)
{
    int i = blockIdx.x * blockDim.x + threadIdx.x;
    if (i < n4) {
        float4 v = in[i];
        out[2 * i + 0] = __floats2half2_rn(v.x, v.y);
        out[2 * i + 1] = __floats2half2_rn(v.z, v.w);
    }
}

__global__ void transpose_half(const float* __restrict__ in, __half* __restrict__ out,
                               int R, int C)
{
    __shared__ float t[32][33];
    int c0 = blockIdx.x * 32, r0 = blockIdx.y * 32;
    int tx = threadIdx.x, ty = threadIdx.y;
    #pragma unroll
    for (int i = 0; i < 32; i += 8)
        t[ty + i][tx] = in[(size_t)(r0 + ty + i) * C + (c0 + tx)];
    __syncthreads();
    #pragma unroll
    for (int i = 0; i < 32; i += 8)
        out[(size_t)(c0 + ty + i) * R + (r0 + tx)] = __float2half_rn(t[tx][ty + i]);
}

__global__ void concat_bias(const float* __restrict__ bq, const float* __restrict__ bk,
                            float* __restrict__ o)
{
    int t = threadIdx.x;
    o[t] = (t < 64) ? bq[t] : bk[t - 64];
}

__global__ void linv_reduce(const float* __restrict__ lpart, float* __restrict__ linv)
{
    int i = blockIdx.x * blockDim.x + threadIdx.x;
    if (i < NB * SEQ) {
        int q = i & (SEQ - 1);
        int nb = (q >> 7) + 1;
        const float* p = lpart + (size_t)i * 16;
        float s = 0.f;
        for (int c = 0; c < nb; c++) s += p[c];
        linv[i] = 1.0f / s;
    }
}

// ---------------------------------------------------------------------------
extern "C" void kernel_launch(void* const* d_in, const int* in_sizes, int n_in,
                              void* d_out, int out_size)
{
    const float* input = (const float*)d_in[0];
    const float* Wq = (const float*)d_in[1];
    const float* bq = (const float*)d_in[2];
    const float* Wk = (const float*)d_in[3];
    const float* bk = (const float*)d_in[4];
    const float* Wv = (const float*)d_in[5];
    const float* bv = (const float*)d_in[6];
    float* out = (float*)d_out;

    __half *Xh, *QKh, *VTh, *Ph, *WqkTh, *WvTh;
    float *Lp, *L, *bqk;
    cudaGetSymbolAddress((void**)&Xh,    g_Xh);
    cudaGetSymbolAddress((void**)&QKh,   g_QKh);
    cudaGetSymbolAddress((void**)&VTh,   g_VTh);
    cudaGetSymbolAddress((void**)&Ph,    g_Ph);
    cudaGetSymbolAddress((void**)&Lp,    g_Lpart);
    cudaGetSymbolAddress((void**)&L,     g_Linv);
    cudaGetSymbolAddress((void**)&WqkTh, g_WqkTh);
    cudaGetSymbolAddress((void**)&WvTh,  g_WvTh);
    cudaGetSymbolAddress((void**)&bqk,   g_bqk);

    auto narrow = mma_gemm<128, 256, 2>;
    auto wide   = mma_gemm<256, 512, 1>;

    static int attrDone = 0;
    if (!attrDone) {
        cudaFuncSetAttribute(narrow, cudaFuncAttributeMaxDynamicSharedMemorySize, 65536);
        cudaFuncSetAttribute(wide,   cudaFuncAttributeMaxDynamicSharedMemorySize, 98304);
        attrDone = 1;
    }
    const int Mrows = NB * SEQ;   // 16384
    dim3 tb(32, 8);

    // pre-passes
    conv_half<<<Mrows * DM / 4 / 256, 256>>>(
        (const float4*)input, (__half2*)Xh, Mrows * DM / 4);
    transpose_half<<<dim3(2, 32), tb>>>(Wq, WqkTh, DM, DK);
    transpose_half<<<dim3(2, 32), tb>>>(Wk, WqkTh + 64 * DM, DM, DK);
    transpose_half<<<dim3(32, 32), tb>>>(Wv, WvTh, DM, DM);
    concat_bias<<<1, 128>>>(bq, bk, bqk);

    // QK = X @ [Wq|Wk] + [bq|bk]  -> half   [16384, 128]
    narrow<<<dim3(1, Mrows / 128), 256, 65536>>>(
        Xh, WqkTh, QKh, bqk, nullptr, nullptr, nullptr,
        128, DM, DM, DM, 0, 0, 1, 0, 0, 0, 0);

    // VT = (X @ Wv + bv)^T -> half [DM, SEQ] per batch (A=WvT, B=X, row bias)
    wide<<<dim3(SEQ / 256, DM / 128, NB), 512, 98304>>>(
        WvTh, Xh, VTh, nullptr, bv, nullptr, nullptr,
        SEQ, DM, DM, DM, 0, 0, 1,
        0, (size_t)SEQ * DM, (size_t)DM * SEQ, 0);

    // P = exp(Q@K^T / 8) diag-masked -> half; partials -> Lpart
    narrow<<<dim3(SEQ / 128, SEQ / 128, NB), 256, 65536>>>(
        QKh, QKh + 64, Ph, nullptr, nullptr, nullptr, Lp,
        SEQ, DK, 128, 128, 0, 1, 2,
        (size_t)SEQ * 128, (size_t)SEQ * 128, (size_t)SEQ * SEQ, 0);

    // Linv = 1 / rowsum
    linv_reduce<<<Mrows / 256, 256>>>(Lp, L);

    // out = diag(Linv) * P @ V   (causal K-limit)   float out
    wide<<<dim3(DM / 256, SEQ / 128, NB), 512, 98304>>>(
        Ph, VTh, out, nullptr, nullptr, L, nullptr,
        DM, SEQ, SEQ, SEQ, 1, 0, 0,
        (size_t)SEQ * SEQ, (size_t)DM * SEQ, (size_t)SEQ * DM, (size_t)SEQ);
}

// round 15
// speedup vs baseline: 1.0751x; 1.0751x over previous
#include <cuda_runtime.h>
#include <cuda_fp16.h>
#include <cstdint>

#define SEQ 2048
#define DM  1024
#define DK  64
#define NB  8

// ------------------------- scratch (device globals) -------------------------
__device__ __half g_Xh [NB * SEQ * DM];               // 32 MB (fp16 input)
__device__ __half g_QKh[NB * SEQ * 128];              //  4 MB (Q cols 0-63, K cols 64-127)
__device__ __half g_VTh[NB * DM * SEQ];               // 32 MB (V^T per batch)
__device__ __half g_Ph [(size_t)NB * SEQ * SEQ];      // 64 MB (P = exp(S/8), masked)
__device__ float  g_Lpart[NB * SEQ * 16];             //  1 MB
__device__ float  g_Linv[NB * SEQ];
__device__ __half g_WqkTh[128 * DM];                  // [Wq|Wk]^T fp16
__device__ __half g_WvTh [DM * DM];                   // Wv^T fp16
__device__ float  g_bqk  [128];

// ------------------------- helpers -------------------------
__device__ __forceinline__ void mma_f16(float* c, const uint32_t* a, const uint32_t* b) {
    asm volatile(
        "mma.sync.aligned.m16n8k16.row.col.f32.f16.f16.f32 "
        "{%0,%1,%2,%3}, {%4,%5,%6,%7}, {%8,%9}, {%0,%1,%2,%3};"
        : "+f"(c[0]), "+f"(c[1]), "+f"(c[2]), "+f"(c[3])
        : "r"(a[0]), "r"(a[1]), "r"(a[2]), "r"(a[3]), "r"(b[0]), "r"(b[1]));
}
__device__ __forceinline__ void ldsm4(uint32_t& r0, uint32_t& r1, uint32_t& r2,
                                      uint32_t& r3, uint32_t addr) {
    asm volatile("ldmatrix.sync.aligned.m8n8.x4.shared.b16 {%0,%1,%2,%3}, [%4];"
        : "=r"(r0), "=r"(r1), "=r"(r2), "=r"(r3) : "r"(addr));
}
__device__ __forceinline__ void cpasync16(uint32_t dst, uint64_t gsrc) {
    asm volatile("cp.async.cg.shared.global [%0], [%1], 16;" :: "r"(dst), "l"(gsrc) : "memory");
}
#define CP_COMMIT() asm volatile("cp.async.commit_group;" ::: "memory")
#define CP_WAIT2()  asm volatile("cp.async.wait_group 2;" ::: "memory")

// Smem tile: [128 rows][32 halves] = 64B/row = 4 16B-units/row.
// unit' = u ^ ((row>>1)&3)  -> cp.async stores and ldmatrix reads conflict-free.
// Stage = A tile (8KB) + B tile (8KB) = 16KB; 4 stages = 64KB dynamic smem.

// ---------------------------------------------------------------------------
// fp16 mma.sync GEMM (m16n8k16), K-major operands in gmem.
//   A: [M x K] half rows lda.  B: [N x K] half rows ldb (B^T effective).
//   outMode: 0 = float C (rowscale+bias+rowbias), 1 = half C (bias+rowbias),
//            2 = scoreExp: half C = exp(acc/8) diag-masked, partials -> lpart
//   BM=128, BN=128, BK=32, 256 thr, 4-stage cp.async pipeline.
// ---------------------------------------------------------------------------
__global__ __launch_bounds__(256, 2)
void mma_gemm(const __half* __restrict__ A, const __half* __restrict__ B,
              void* __restrict__ Cv, const float* __restrict__ bias,
              const float* __restrict__ rowbias,
              const float* __restrict__ rowscale, float* __restrict__ lpart,
              int N, int K, int lda, int ldb,
              int causalK, int causalSkip, int outMode,
              size_t sA, size_t sB, size_t sC, size_t sR)
{
    extern __shared__ uint32_t SM[];

    const int rb = blockIdx.y, cb = blockIdx.x, z = blockIdx.z;
    if (causalSkip && cb > rb) return;

    A += (size_t)z * sA;
    B += (size_t)z * sB;
    if (rowscale) rowscale += (size_t)z * sR;

    int kend = causalK ? (rb + 1) * 128 : K;
    if (kend > K) kend = K;
    const int NC = kend >> 5;

    const int tid = threadIdx.x, lane = tid & 31;
    const int wm = (tid >> 5) >> 1;      // 0..3
    const int wn = (tid >> 5) & 1;       // 0..1

    const __half* Ab = A + (size_t)rb * 128 * lda;
    const __half* Bb = B + (size_t)cb * 128 * ldb;
    uint64_t gAb, gBb;
    asm("cvta.to.global.u64 %0, %1;" : "=l"(gAb) : "l"(Ab));
    asm("cvta.to.global.u64 %0, %1;" : "=l"(gBb) : "l"(Bb));
    const uint32_t smb = (uint32_t)__cvta_generic_to_shared(SM);

    // cp.async slots: thread covers (row r, unit u) for A and B (2 each)
    uint32_t dstA[2], dstB[2];
    uint64_t offA[2], offB[2];
    #pragma unroll
    for (int it = 0; it < 2; it++) {
        int f = tid + it * 256;
        int r = f >> 2, u = f & 3;
        uint32_t sw = (uint32_t)(r * 64 + ((u ^ ((r >> 1) & 3)) << 4));
        dstA[it] = smb + sw;
        dstB[it] = smb + 8192u + sw;
        offA[it] = ((uint64_t)r * lda + (uint64_t)u * 8) * 2u;
        offB[it] = ((uint64_t)r * ldb + (uint64_t)u * 8) * 2u;
    }

    // ldmatrix addresses (stage 0); in-loop +stage*16384
    uint32_t adrA[2][2], adrB[4][2];
    {
        const int rl = ((lane >> 3) & 1) * 8 + (lane & 7);
        const int cl = (lane >> 4) & 1;
        #pragma unroll
        for (int mi = 0; mi < 2; mi++) {
            int r = wm * 32 + mi * 16 + rl;
            #pragma unroll
            for (int ks = 0; ks < 2; ks++) {
                int u = 2 * ks + cl;
                adrA[mi][ks] = smb + (uint32_t)(r * 64 + ((u ^ ((r >> 1) & 3)) << 4));
            }
        }
        #pragma unroll
        for (int p = 0; p < 4; p++) {
            int n = wn * 64 + p * 16 + rl;
            #pragma unroll
            for (int ks = 0; ks < 2; ks++) {
                int u = 2 * ks + cl;
                adrB[p][ks] = smb + 8192u + (uint32_t)(n * 64 + ((u ^ ((n >> 1) & 3)) << 4));
            }
        }
    }

    float acc[2][8][4];
    #pragma unroll
    for (int i = 0; i < 2; i++)
        #pragma unroll
        for (int j = 0; j < 8; j++)
            #pragma unroll
            for (int q = 0; q < 4; q++) acc[i][j][q] = 0.f;

    auto issue = [&](int c, int stg) {
        const uint32_t so = (uint32_t)stg * 16384u;
        const uint64_t co = (uint64_t)c * 64u;   // 32 halves along K
        #pragma unroll
        for (int it = 0; it < 2; it++)
            cpasync16(dstA[it] + so, gAb + co + offA[it]);
        #pragma unroll
        for (int it = 0; it < 2; it++)
            cpasync16(dstB[it] + so, gBb + co + offB[it]);
    };

    auto compute = [&](int stg) {
        const uint32_t bo = (uint32_t)stg * 16384u;
        #pragma unroll
        for (int ks = 0; ks < 2; ks++) {
            uint32_t a[2][4], b[8][2];
            #pragma unroll
            for (int mi = 0; mi < 2; mi++)
                ldsm4(a[mi][0], a[mi][1], a[mi][2], a[mi][3], adrA[mi][ks] + bo);
            #pragma unroll
            for (int p = 0; p < 4; p++)
                ldsm4(b[2 * p][0], b[2 * p + 1][0], b[2 * p][1], b[2 * p + 1][1],
                      adrB[p][ks] + bo);
            #pragma unroll
            for (int mi = 0; mi < 2; mi++)
                #pragma unroll
                for (int ni = 0; ni < 8; ni++)
                    mma_f16(acc[mi][ni], a[mi], b[ni]);
        }
    };

    #pragma unroll
    for (int s = 0; s < 3; s++) {
        if (s < NC) issue(s, s);
        CP_COMMIT();
    }
    for (int c = 0; c < NC; c++) {
        CP_WAIT2();
        __syncthreads();
        compute(c & 3);
        const int nc = c + 3;
        if (nc < NC) issue(nc, nc & 3);
        CP_COMMIT();
    }

    // ---------------- epilogue ----------------
    if (outMode == 2) {
        __half* C = (__half*)Cv + (size_t)z * sC;
        const bool diag = (cb == rb);
        float part[2][2] = {{0.f, 0.f}, {0.f, 0.f}};
        #pragma unroll
        for (int mi = 0; mi < 2; mi++) {
            int rbase = rb * 128 + wm * 32 + mi * 16 + (lane >> 2);
            #pragma unroll
            for (int half_ = 0; half_ < 2; half_++) {
                int row = rbase + half_ * 8;
                __half* Cp = C + (size_t)row * N;
                #pragma unroll
                for (int ni = 0; ni < 8; ni++) {
                    int col = cb * 128 + wn * 64 + ni * 8 + ((lane & 3) << 1);
                    float e0 = __expf(acc[mi][ni][half_ * 2 + 0] * 0.125f);
                    float e1 = __expf(acc[mi][ni][half_ * 2 + 1] * 0.125f);
                    if (diag) {
                        if (col > row) e0 = 0.f;
                        if (col + 1 > row) e1 = 0.f;
                    }
                    part[mi][half_] += e0 + e1;
                    *reinterpret_cast<__half2*>(Cp + col) = __floats2half2_rn(e0, e1);
                }
            }
        }
        __syncthreads();
        float* rs = reinterpret_cast<float*>(SM);   // [128][2]
        #pragma unroll
        for (int mi = 0; mi < 2; mi++)
            #pragma unroll
            for (int half_ = 0; half_ < 2; half_++) {
                float v = part[mi][half_];
                v += __shfl_xor_sync(0xFFFFFFFF, v, 1);
                v += __shfl_xor_sync(0xFFFFFFFF, v, 2);
                if ((lane & 3) == 0) {
                    int rl = wm * 32 + mi * 16 + half_ * 8 + (lane >> 2);
                    rs[rl * 2 + wn] = v;
                }
            }
        __syncthreads();
        if (tid < 128)
            lpart[(((size_t)z * SEQ) + rb * 128 + tid) * 16 + cb] =
                rs[tid * 2] + rs[tid * 2 + 1];
        return;
    }

    #pragma unroll
    for (int mi = 0; mi < 2; mi++) {
        int rbase = rb * 128 + wm * 32 + mi * 16 + (lane >> 2);
        #pragma unroll
        for (int half_ = 0; half_ < 2; half_++) {
            int row = rbase + half_ * 8;
            float sc = rowscale ? rowscale[row] : 1.0f;
            float rbv = rowbias ? rowbias[row] : 0.0f;
            #pragma unroll
            for (int ni = 0; ni < 8; ni++) {
                int col = cb * 128 + wn * 64 + ni * 8 + ((lane & 3) << 1);
                float b0 = rbv, b1 = rbv;
                if (bias) { b0 += bias[col]; b1 += bias[col + 1]; }
                float o0 = acc[mi][ni][half_ * 2 + 0] * sc + b0;
                float o1 = acc[mi][ni][half_ * 2 + 1] * sc + b1;
                if (outMode == 1) {
                    __half* Cp = (__half*)Cv + (size_t)z * sC + (size_t)row * N;
                    *reinterpret_cast<__half2*>(Cp + col) = __floats2half2_rn(o0, o1);
                } else {
                    float* Cp = (float*)Cv + (size_t)z * sC + (size_t)row * N;
                    *reinterpret_cast<float2*>(Cp + col) = make_float2(o0, o1);
                }
            }
        }
    }
}

// ---------------------------------------------------------------------------
__global__ void conv_half(const float4* __restrict__ in, __half2* __restrict__ out, int n4)
{
    int i = blockIdx.x * blockDim.x + threadIdx.x;
    if (i < n4) {
        float4 v = in[i];
        out[2 * i + 0] = __floats2half2_rn(v.x, v.y);
        out[2 * i + 1] = __floats2half2_rn(v.z, v.w);
    }
}

__global__ void transpose_half(const float* __restrict__ in, __half* __restrict__ out,
                               int R, int C)
{
    __shared__ float t[32][33];
    int c0 = blockIdx.x * 32, r0 = blockIdx.y * 32;
    int tx = threadIdx.x, ty = threadIdx.y;
    #pragma unroll
    for (int i = 0; i < 32; i += 8)
        t[ty + i][tx] = in[(size_t)(r0 + ty + i) * C + (c0 + tx)];
    __syncthreads();
    #pragma unroll
    for (int i = 0; i < 32; i += 8)
        out[(size_t)(c0 + ty + i) * R + (r0 + tx)] = __float2half_rn(t[tx][ty + i]);
}

__global__ void concat_bias(const float* __restrict__ bq, const float* __restrict__ bk,
                            float* __restrict__ o)
{
    int t = threadIdx.x;
    o[t] = (t < 64) ? bq[t] : bk[t - 64];
}

__global__ void linv_reduce(const float* __restrict__ lpart, float* __restrict__ linv)
{
    int i = blockIdx.x * blockDim.x + threadIdx.x;
    if (i < NB * SEQ) {
        int q = i & (SEQ - 1);
        int nb = (q >> 7) + 1;
        const float* p = lpart + (size_t)i * 16;
        float s = 0.f;
        for (int c = 0; c < nb; c++) s += p[c];
        linv[i] = 1.0f / s;
    }
}

// ---------------------------------------------------------------------------
extern "C" void kernel_launch(void* const* d_in, const int* in_sizes, int n_in,
                              void* d_out, int out_size)
{
    const float* input = (const float*)d_in[0];
    const float* Wq = (const float*)d_in[1];
    const float* bq = (const float*)d_in[2];
    const float* Wk = (const float*)d_in[3];
    const float* bk = (const float*)d_in[4];
    const float* Wv = (const float*)d_in[5];
    const float* bv = (const float*)d_in[6];
    float* out = (float*)d_out;

    __half *Xh, *QKh, *VTh, *Ph, *WqkTh, *WvTh;
    float *Lp, *L, *bqk;
    cudaGetSymbolAddress((void**)&Xh,    g_Xh);
    cudaGetSymbolAddress((void**)&QKh,   g_QKh);
    cudaGetSymbolAddress((void**)&VTh,   g_VTh);
    cudaGetSymbolAddress((void**)&Ph,    g_Ph);
    cudaGetSymbolAddress((void**)&Lp,    g_Lpart);
    cudaGetSymbolAddress((void**)&L,     g_Linv);
    cudaGetSymbolAddress((void**)&WqkTh, g_WqkTh);
    cudaGetSymbolAddress((void**)&WvTh,  g_WvTh);
    cudaGetSymbolAddress((void**)&bqk,   g_bqk);

    static int inited = 0;
    static cudaStream_t s1;
    static cudaEvent_t evFork, evConv, evV;
    if (!inited) {
        cudaFuncSetAttribute(mma_gemm, cudaFuncAttributeMaxDynamicSharedMemorySize, 65536);
        cudaStreamCreateWithFlags(&s1, cudaStreamNonBlocking);
        cudaEventCreateWithFlags(&evFork, cudaEventDisableTiming);
        cudaEventCreateWithFlags(&evConv, cudaEventDisableTiming);
        cudaEventCreateWithFlags(&evV,    cudaEventDisableTiming);
        inited = 1;
    }
    const int SMEMB = 65536;
    const int Mrows = NB * SEQ;   // 16384
    dim3 tb(32, 8);

    // fork side branch off the capture stream
    cudaEventRecord(evFork, 0);
    cudaStreamWaitEvent(s1, evFork, 0);

    // ---- main branch (stream 0) ----
    conv_half<<<Mrows * DM / 4 / 256, 256>>>(
        (const float4*)input, (__half2*)Xh, Mrows * DM / 4);
    cudaEventRecord(evConv, 0);
    transpose_half<<<dim3(2, 32), tb>>>(Wq, WqkTh, DM, DK);
    transpose_half<<<dim3(2, 32), tb>>>(Wk, WqkTh + 64 * DM, DM, DK);
    concat_bias<<<1, 128>>>(bq, bk, bqk);

    // ---- side branch (s1): Wv transpose + V projection ----
    transpose_half<<<dim3(32, 32), tb, 0, s1>>>(Wv, WvTh, DM, DM);
    cudaStreamWaitEvent(s1, evConv, 0);
    mma_gemm<<<dim3(SEQ / 128, DM / 128, NB), 256, SMEMB, s1>>>(
        WvTh, Xh, VTh, nullptr, bv, nullptr, nullptr,
        SEQ, DM, DM, DM, 0, 0, 1,
        0, (size_t)SEQ * DM, (size_t)DM * SEQ, 0);
    cudaEventRecord(evV, s1);

    // ---- main branch continues ----
    // QK = X @ [Wq|Wk] + [bq|bk]  -> half   [16384, 128]
    mma_gemm<<<dim3(1, Mrows / 128), 256, SMEMB>>>(
        Xh, WqkTh, QKh, bqk, nullptr, nullptr, nullptr,
        128, DM, DM, DM, 0, 0, 1, 0, 0, 0, 0);

    // P = exp(Q@K^T / 8) diag-masked -> half; partials -> Lpart
    mma_gemm<<<dim3(SEQ / 128, SEQ / 128, NB), 256, SMEMB>>>(
        QKh, QKh + 64, Ph, nullptr, nullptr, nullptr, Lp,
        SEQ, DK, 128, 128, 0, 1, 2,
        (size_t)SEQ * 128, (size_t)SEQ * 128, (size_t)SEQ * SEQ, 0);

    // Linv = 1 / rowsum
    linv_reduce<<<Mrows / 256, 256>>>(Lp, L);

    // join: PV needs VT
    cudaStreamWaitEvent(0, evV, 0);

    // out = diag(Linv) * P @ V   (causal K-limit)   float out
    mma_gemm<<<dim3(DM / 128, SEQ / 128, NB), 256, SMEMB>>>(
        Ph, VTh, out, nullptr, nullptr, L, nullptr,
        DM, SEQ, SEQ, SEQ, 1, 0, 0,
        (size_t)SEQ * SEQ, (size_t)DM * SEQ, (size_t)SEQ * DM, (size_t)SEQ);
}